// round 16
// baseline (speedup 1.0000x reference)
#include <cuda_runtime.h>
#include <cuda_fp16.h>
#include <math.h>
#include <stdint.h>

// Problem constants
#define BV 32
#define TT 256
#define EE 384
#define HH 6
#define DD 64
#define LL 6
#define FF 1536
#define VVOC 32000
#define MM (BV*TT)   // 8192
#define E3 (3*EE)    // 1152

// ---------------- scratch ----------------
__device__ float  g_x   [MM*EE];
__device__ __half g_qkv [MM*E3];
__device__ __half g_h   [MM*EE];
__device__ __half g_ao  [MM*EE];
__device__ __half g_ff  [(size_t)MM*FF];
__device__ __half g_wqkv[LL*EE*E3];
__device__ __half g_wo  [LL*EE*EE];
__device__ __half g_w1  [LL*EE*FF];
__device__ __half g_w2  [LL*FF*EE];
__device__ __half g_wh  [(size_t)EE*VVOC];

// ---------------- PTX helpers ----------------
__device__ __forceinline__ void cp_async16(uint32_t dst, const void* src) {
    asm volatile("cp.async.cg.shared.global [%0], [%1], 16;" :: "r"(dst), "l"(src));
}
__device__ __forceinline__ void cp_commit() { asm volatile("cp.async.commit_group;"); }
template<int N>
__device__ __forceinline__ void cp_wait() { asm volatile("cp.async.wait_group %0;" :: "n"(N)); }

__device__ __forceinline__ void ldsm_x4(uint32_t* r, uint32_t a) {
    asm volatile("ldmatrix.sync.aligned.m8n8.x4.shared.b16 {%0,%1,%2,%3}, [%4];"
        : "=r"(r[0]), "=r"(r[1]), "=r"(r[2]), "=r"(r[3]) : "r"(a));
}
__device__ __forceinline__ void ldsm_x4_t(uint32_t* r, uint32_t a) {
    asm volatile("ldmatrix.sync.aligned.m8n8.x4.trans.shared.b16 {%0,%1,%2,%3}, [%4];"
        : "=r"(r[0]), "=r"(r[1]), "=r"(r[2]), "=r"(r[3]) : "r"(a));
}
__device__ __forceinline__ void mma_f16(float* c, const uint32_t* a, const uint32_t* b) {
    asm volatile(
        "mma.sync.aligned.m16n8k16.row.col.f32.f16.f16.f32 "
        "{%0,%1,%2,%3}, {%4,%5,%6,%7}, {%8,%9}, {%0,%1,%2,%3};"
        : "+f"(c[0]), "+f"(c[1]), "+f"(c[2]), "+f"(c[3])
        : "r"(a[0]), "r"(a[1]), "r"(a[2]), "r"(a[3]), "r"(b[0]), "r"(b[1]));
}

// ---------------- embedding ----------------
__global__ void embed_kernel(const int* __restrict__ idx, const float* __restrict__ tok,
                             const float* __restrict__ pos, float* __restrict__ x)
{
    int i = blockIdx.x * blockDim.x + threadIdx.x;
    if (i >= MM*EE) return;
    int e   = i % EE;
    int row = i / EE;
    int t   = row % TT;
    x[i] = tok[(size_t)idx[row]*EE + e] + pos[t*EE + e];
}

// ---------------- weight prep (vectorized x2) ----------------
__global__ void pack_qkv_half(const float* __restrict__ Wq, const float* __restrict__ Wk,
                              const float* __restrict__ Wv, __half* __restrict__ out)
{
    int i = blockIdx.x * blockDim.x + threadIdx.x;   // pair index
    if (i >= LL*EE*E3/2) return;
    int e2 = i * 2;
    int c  = e2 % E3;
    int re = e2 / E3;
    int sel = c / EE;       // pair never straddles a 384 boundary
    int cc  = c % EE;
    const float* src = (sel == 0) ? Wq : (sel == 1) ? Wk : Wv;
    float2 v = *(const float2*)(src + (size_t)re*EE + cc);
    *(__half2*)(out + e2) = __floats2half2_rn(v.x, v.y);
}

__global__ void prep4_kernel(const float* __restrict__ Wo, const float* __restrict__ W1,
                             const float* __restrict__ W2, const float* __restrict__ Wh,
                             __half* __restrict__ wo, __half* __restrict__ w1,
                             __half* __restrict__ w2, __half* __restrict__ wh)
{
    const int N0 = LL*EE*EE/2, N1 = LL*EE*FF/2, N2 = LL*FF*EE/2;
    const int NH = EE*VVOC/2;
    int i = blockIdx.x * blockDim.x + threadIdx.x;
    const float* s; __half* d;
    if      (i < N0)                 { s = Wo; d = wo; }
    else if ((i -= N0) < N1)         { s = W1; d = w1; }
    else if ((i -= N1) < N2)         { s = W2; d = w2; }
    else if ((i -= N2) < NH)         { s = Wh; d = wh; }
    else return;
    float2 v = *(const float2*)(s + (size_t)i*2);
    *(__half2*)(d + (size_t)i*2) = __floats2half2_rn(v.x, v.y);
}

// ---------------- layernorm: one warp per row ----------------
__global__ void ln_kernel(const float* __restrict__ in, __half* __restrict__ out,
                          const float* __restrict__ s, const float* __restrict__ b)
{
    int warp = threadIdx.x >> 5, lane = threadIdx.x & 31;
    int row  = blockIdx.x * 8 + warp;
    const float4* xr = (const float4*)(in + (size_t)row*EE);
    float4 v[3];
    float ls = 0.f, lq = 0.f;
    #pragma unroll
    for (int k = 0; k < 3; k++) {
        v[k] = xr[lane + 32*k];
        ls += (v[k].x + v[k].y) + (v[k].z + v[k].w);
        lq += (v[k].x*v[k].x + v[k].y*v[k].y) + (v[k].z*v[k].z + v[k].w*v[k].w);
    }
    #pragma unroll
    for (int o = 16; o > 0; o >>= 1) {
        ls += __shfl_xor_sync(0xffffffffu, ls, o);
        lq += __shfl_xor_sync(0xffffffffu, lq, o);
    }
    float mean = ls * (1.0f/EE);
    float var  = lq * (1.0f/EE) - mean*mean;
    float inv  = rsqrtf(var + 1e-5f);
    #pragma unroll
    for (int k = 0; k < 3; k++) {
        int c4 = lane + 32*k;
        float4 s4 = ((const float4*)s)[c4];
        float4 b4 = ((const float4*)b)[c4];
        float o0 = (v[k].x - mean) * inv * s4.x + b4.x;
        float o1 = (v[k].y - mean) * inv * s4.y + b4.y;
        float o2 = (v[k].z - mean) * inv * s4.z + b4.z;
        float o3 = (v[k].w - mean) * inv * s4.w + b4.w;
        __half2* op = (__half2*)(out + (size_t)row*EE + c4*4);
        op[0] = __floats2half2_rn(o0, o1);
        op[1] = __floats2half2_rn(o2, o3);
    }
}

// ---------------- fp16 tensor-core GEMM (BM=128, BN=128, warp 32x64) ----------------
// MODE: 0 = f32 store, 1 = f32 accumulate into C, 2 = relu->fp16, 3 = fp16 store
#define ATILE 16384

template<int BN, int MODE>
__global__ void __launch_bounds__(256, 2)
hgemm_kernel(const __half* __restrict__ A, const __half* __restrict__ B,
             const float* __restrict__ bias, void* __restrict__ Cv,
             int M, int N, int K)
{
    constexpr int T     = 256;
    constexpr int NST   = 3;
    constexpr int BTILE = 64 * BN * 2;
    constexpr int STAGE = ATILE + BTILE;
    constexpr int ITERA = 1024 / T;
    constexpr int ITERB = (8 * BN) / T;

    extern __shared__ char smem[];
    const uint32_t sb = (uint32_t)__cvta_generic_to_shared(smem);

    const int tid  = threadIdx.x;
    const int lane = tid & 31;
    const int wid  = tid >> 5;
    const int wm   = wid & 3;
    const int wn   = wid >> 2;
    const int g    = lane >> 2;
    const int t    = lane & 3;

    const int row0 = blockIdx.y * 128;
    const int col0 = blockIdx.x * BN;
    const int KT   = K >> 6;

    auto issue = [&](int kt) {
        uint32_t st = sb + (uint32_t)(kt % NST) * STAGE;
        #pragma unroll
        for (int i = 0; i < ITERA; i++) {
            int c = tid + T*i;
            int r = c >> 3, gg = c & 7;
            cp_async16(st + r*128 + 16*(gg ^ (r&7)),
                       A + (size_t)(row0 + r)*K + kt*64 + gg*8);
        }
        #pragma unroll
        for (int i = 0; i < ITERB; i++) {
            int c = tid + T*i;
            int k = c / (BN/8), gg = c % (BN/8);
            cp_async16(st + ATILE + k*(BN*2) + 16*(gg ^ (k&7)),
                       B + (size_t)(kt*64 + k)*N + col0 + gg*8);
        }
        cp_commit();
    };

    float acc[2][8][4];
    #pragma unroll
    for (int mi = 0; mi < 2; mi++)
        #pragma unroll
        for (int ni = 0; ni < 8; ni++)
            #pragma unroll
            for (int r = 0; r < 4; r++) acc[mi][ni][r] = 0.f;

    issue(0); issue(1);

    for (int kt = 0; kt < KT; kt++) {
        cp_wait<1>();
        __syncthreads();
        if (kt + 2 < KT) issue(kt + 2);

        const uint32_t a_st = sb + (uint32_t)(kt % NST) * STAGE;
        const uint32_t b_st = a_st + ATILE;

        #pragma unroll
        for (int ks = 0; ks < 4; ks++) {
            uint32_t af[2][4], bf[8][2];
            #pragma unroll
            for (int mi = 0; mi < 2; mi++) {
                int m  = wm*32 + mi*16 + (lane & 15);
                int gg = ks*2 + (lane >> 4);
                ldsm_x4(af[mi], a_st + m*128 + 16*(gg ^ (m&7)));
            }
            #pragma unroll
            for (int np = 0; np < 4; np++) {
                int k  = ks*16 + (lane & 15);
                int gg = (wn*64 + np*16)/8 + (lane >> 4);
                uint32_t tmp[4];
                ldsm_x4_t(tmp, b_st + k*(BN*2) + 16*(gg ^ (k&7)));
                bf[np*2][0]   = tmp[0]; bf[np*2][1]   = tmp[1];
                bf[np*2+1][0] = tmp[2]; bf[np*2+1][1] = tmp[3];
            }
            #pragma unroll
            for (int mi = 0; mi < 2; mi++)
                #pragma unroll
                for (int ni = 0; ni < 8; ni++)
                    mma_f16(acc[mi][ni], af[mi], bf[ni]);
        }
    }

    __syncthreads();

    #pragma unroll
    for (int mi = 0; mi < 2; mi++) {
        #pragma unroll
        for (int ni = 0; ni < 8; ni++) {
            int row = row0 + wm*32 + mi*16 + g;
            int col = col0 + wn*64 + ni*8 + t*2;
            float v0 = acc[mi][ni][0], v1 = acc[mi][ni][1];
            float v2 = acc[mi][ni][2], v3 = acc[mi][ni][3];
            if (bias) {
                float b0 = bias[col], b1 = bias[col+1];
                v0 += b0; v1 += b1; v2 += b0; v3 += b1;
            }
            if (MODE == 2 || MODE == 3) {
                if (MODE == 2) {
                    v0 = fmaxf(v0, 0.f); v1 = fmaxf(v1, 0.f);
                    v2 = fmaxf(v2, 0.f); v3 = fmaxf(v3, 0.f);
                }
                __half* C = (__half*)Cv;
                *(__half2*)(C + (size_t)row * N + col)     = __floats2half2_rn(v0, v1);
                *(__half2*)(C + (size_t)(row+8) * N + col) = __floats2half2_rn(v2, v3);
            } else {
                float* C = (float*)Cv;
                float* c0 = C + (size_t)row * N + col;
                float* c1 = C + (size_t)(row + 8) * N + col;
                if (MODE == 1) {
                    float2 o0 = *(const float2*)c0;
                    float2 o1 = *(const float2*)c1;
                    v0 += o0.x; v1 += o0.y; v2 += o1.x; v3 += o1.y;
                }
                *(float2*)c0 = make_float2(v0, v1);
                *(float2*)c1 = make_float2(v2, v3);
            }
        }
    }
}

// ---------------- fp16 GEMM wide: BM=128 x BN=256, 8 warps, warp tile 64x64 ----
// NST=4 deep pipeline (2 warps/SMSP needs the extra slack).
// MODE: 0 = f32 store (+bias), 2 = relu -> fp16 store (+bias)
#define BTILEW (64*256*2)          // 32768
#define STAGEW (ATILE + BTILEW)    // 49152
#define NSTW 4
#define SMW (NSTW*STAGEW)          // 196608

template<int MODE>
__global__ void __launch_bounds__(256, 1)
hgemm_wide_kernel(const __half* __restrict__ A, const __half* __restrict__ B,
                  const float* __restrict__ bias, void* __restrict__ Cv,
                  int M, int N, int K)
{
    extern __shared__ char smem[];
    const uint32_t sb = (uint32_t)__cvta_generic_to_shared(smem);

    const int tid  = threadIdx.x;
    const int lane = tid & 31;
    const int wid  = tid >> 5;
    const int wm   = wid >> 2;
    const int wn   = wid & 3;
    const int g    = lane >> 2;
    const int t    = lane & 3;

    const int row0 = blockIdx.y * 128;
    const int col0 = blockIdx.x * 256;
    const int KT   = K >> 6;

    auto issue = [&](int kt) {
        uint32_t st = sb + (uint32_t)(kt % NSTW) * STAGEW;
        #pragma unroll
        for (int i = 0; i < 4; i++) {
            int c = tid + 256*i;
            int r = c >> 3, gg = c & 7;
            cp_async16(st + r*128 + 16*(gg ^ (r&7)),
                       A + (size_t)(row0 + r)*K + kt*64 + gg*8);
        }
        #pragma unroll
        for (int i = 0; i < 8; i++) {
            int c = tid + 256*i;
            int k = c >> 5, gg = c & 31;
            cp_async16(st + ATILE + k*512 + 16*(gg ^ (k&7)),
                       B + (size_t)(kt*64 + k)*N + col0 + gg*8);
        }
        cp_commit();
    };

    float acc[4][8][4];
    #pragma unroll
    for (int mi = 0; mi < 4; mi++)
        #pragma unroll
        for (int ni = 0; ni < 8; ni++)
            #pragma unroll
            for (int r = 0; r < 4; r++) acc[mi][ni][r] = 0.f;

    issue(0); issue(1); issue(2);

    for (int kt = 0; kt < KT; kt++) {
        cp_wait<2>();
        __syncthreads();
        if (kt + 3 < KT) issue(kt + 3);

        const uint32_t a_st = sb + (uint32_t)(kt % NSTW) * STAGEW;
        const uint32_t b_st = a_st + ATILE;

        #pragma unroll
        for (int ks = 0; ks < 4; ks++) {
            uint32_t af[4][4], bf[8][2];
            #pragma unroll
            for (int mi = 0; mi < 4; mi++) {
                int m  = wm*64 + mi*16 + (lane & 15);
                int gg = ks*2 + (lane >> 4);
                ldsm_x4(af[mi], a_st + m*128 + 16*(gg ^ (m&7)));
            }
            #pragma unroll
            for (int np = 0; np < 4; np++) {
                int k  = ks*16 + (lane & 15);
                int gg = wn*8 + np*2 + (lane >> 4);
                uint32_t tmp[4];
                ldsm_x4_t(tmp, b_st + k*512 + 16*(gg ^ (k&7)));
                bf[np*2][0]   = tmp[0]; bf[np*2][1]   = tmp[1];
                bf[np*2+1][0] = tmp[2]; bf[np*2+1][1] = tmp[3];
            }
            #pragma unroll
            for (int mi = 0; mi < 4; mi++)
                #pragma unroll
                for (int ni = 0; ni < 8; ni++)
                    mma_f16(acc[mi][ni], af[mi], bf[ni]);
        }
    }

    __syncthreads();

    #pragma unroll
    for (int mi = 0; mi < 4; mi++) {
        #pragma unroll
        for (int ni = 0; ni < 8; ni++) {
            int row = row0 + wm*64 + mi*16 + g;
            int col = col0 + wn*64 + ni*8 + t*2;
            float v0 = acc[mi][ni][0], v1 = acc[mi][ni][1];
            float v2 = acc[mi][ni][2], v3 = acc[mi][ni][3];
            if (bias) {
                float b0 = bias[col], b1 = bias[col+1];
                v0 += b0; v1 += b1; v2 += b0; v3 += b1;
            }
            if (MODE == 2) {
                v0 = fmaxf(v0, 0.f); v1 = fmaxf(v1, 0.f);
                v2 = fmaxf(v2, 0.f); v3 = fmaxf(v3, 0.f);
                __half* C = (__half*)Cv;
                *(__half2*)(C + (size_t)row * N + col)     = __floats2half2_rn(v0, v1);
                *(__half2*)(C + (size_t)(row+8) * N + col) = __floats2half2_rn(v2, v3);
            } else {
                float* C = (float*)Cv;
                *(float2*)(C + (size_t)row * N + col)       = make_float2(v0, v1);
                *(float2*)(C + (size_t)(row + 8) * N + col) = make_float2(v2, v3);
            }
        }
    }
}

// ---------------- fp16 GEMM, BM=64 x BN=128 (wave-friendly, accumulate mode) ----
#define ATILE64 8192
#define STAGE64 (ATILE64 + 16384)

__global__ void __launch_bounds__(256, 2)
hgemm64_kernel(const __half* __restrict__ A, const __half* __restrict__ B,
               const float* __restrict__ bias, float* __restrict__ C,
               int M, int N, int K)
{
    constexpr int NST = 3;
    extern __shared__ char smem[];
    const uint32_t sb = (uint32_t)__cvta_generic_to_shared(smem);

    const int tid  = threadIdx.x;
    const int lane = tid & 31;
    const int wid  = tid >> 5;
    const int wm   = wid & 1;
    const int wn   = wid >> 1;
    const int g    = lane >> 2;
    const int t    = lane & 3;

    const int row0 = blockIdx.y * 64;
    const int col0 = blockIdx.x * 128;
    const int KT   = K >> 6;

    auto issue = [&](int kt) {
        uint32_t st = sb + (uint32_t)(kt % NST) * STAGE64;
        #pragma unroll
        for (int i = 0; i < 2; i++) {
            int c = tid + 256*i;
            int r = c >> 3, gg = c & 7;
            cp_async16(st + r*128 + 16*(gg ^ (r&7)),
                       A + (size_t)(row0 + r)*K + kt*64 + gg*8);
        }
        #pragma unroll
        for (int i = 0; i < 4; i++) {
            int c = tid + 256*i;
            int k = c >> 4, gg = c & 15;
            cp_async16(st + ATILE64 + k*256 + 16*(gg ^ (k&7)),
                       B + (size_t)(kt*64 + k)*N + col0 + gg*8);
        }
        cp_commit();
    };

    float acc[2][4][4];
    #pragma unroll
    for (int mi = 0; mi < 2; mi++)
        #pragma unroll
        for (int ni = 0; ni < 4; ni++)
            #pragma unroll
            for (int r = 0; r < 4; r++) acc[mi][ni][r] = 0.f;

    issue(0); issue(1);

    for (int kt = 0; kt < KT; kt++) {
        cp_wait<1>();
        __syncthreads();
        if (kt + 2 < KT) issue(kt + 2);

        const uint32_t a_st = sb + (uint32_t)(kt % NST) * STAGE64;
        const uint32_t b_st = a_st + ATILE64;

        #pragma unroll
        for (int ks = 0; ks < 4; ks++) {
            uint32_t af[2][4], bf[4][2];
            #pragma unroll
            for (int mi = 0; mi < 2; mi++) {
                int m  = wm*32 + mi*16 + (lane & 15);
                int gg = ks*2 + (lane >> 4);
                ldsm_x4(af[mi], a_st + m*128 + 16*(gg ^ (m&7)));
            }
            #pragma unroll
            for (int np = 0; np < 2; np++) {
                int k  = ks*16 + (lane & 15);
                int gg = (wn*32 + np*16)/8 + (lane >> 4);
                uint32_t tmp[4];
                ldsm_x4_t(tmp, b_st + k*256 + 16*(gg ^ (k&7)));
                bf[np*2][0]   = tmp[0]; bf[np*2][1]   = tmp[1];
                bf[np*2+1][0] = tmp[2]; bf[np*2+1][1] = tmp[3];
            }
            #pragma unroll
            for (int mi = 0; mi < 2; mi++)
                #pragma unroll
                for (int ni = 0; ni < 4; ni++)
                    mma_f16(acc[mi][ni], af[mi], bf[ni]);
        }
    }

    __syncthreads();

    #pragma unroll
    for (int mi = 0; mi < 2; mi++) {
        #pragma unroll
        for (int ni = 0; ni < 4; ni++) {
            int row = row0 + wm*32 + mi*16 + g;
            int col = col0 + wn*32 + ni*8 + t*2;
            float v0 = acc[mi][ni][0], v1 = acc[mi][ni][1];
            float v2 = acc[mi][ni][2], v3 = acc[mi][ni][3];
            if (bias) {
                float b0 = bias[col], b1 = bias[col+1];
                v0 += b0; v1 += b1; v2 += b0; v3 += b1;
            }
            float* c0 = C + (size_t)row * N + col;
            float* c1 = C + (size_t)(row + 8) * N + col;
            float2 o0 = *(const float2*)c0;
            float2 o1 = *(const float2*)c1;
            *(float2*)c0 = make_float2(v0 + o0.x, v1 + o0.y);
            *(float2*)c1 = make_float2(v2 + o1.x, v3 + o1.y);
        }
    }
}

// ---------------- flash attention: 512 threads, one 16-row tile per warp ----
#define FA_SMEM 98304

__global__ void __launch_bounds__(512, 2)
fattn_kernel(const __half* __restrict__ qkv, __half* __restrict__ o)
{
    extern __shared__ char sm[];
    const uint32_t sb = (uint32_t)__cvta_generic_to_shared(sm);
    const uint32_t Qs = sb, Ks = sb + 32768, Vs = sb + 65536;

    const int b = blockIdx.x / HH;
    const int h = blockIdx.x % HH;
    const int tid  = threadIdx.x;
    const int lane = tid & 31;
    const int w    = tid >> 5;
    const int g    = lane >> 2;
    const int t    = lane & 3;

    const __half* base = qkv + (size_t)b*TT*E3 + h*DD;
    #pragma unroll
    for (int i = 0; i < 12; i++) {
        int idx = tid + 512*i;
        int sec = idx >> 11;
        int rem = idx & 2047;
        int seq = rem >> 3, c8 = rem & 7;
        uint32_t dst = sb + sec*32768 + seq*128 + 16*(c8 ^ (seq & 7));
        cp_async16(dst, base + (size_t)seq*E3 + sec*EE + c8*8);
    }
    cp_commit();
    cp_wait<0>();
    __syncthreads();

    const float kscale = 0.125f * 1.44269504f;
    uint32_t onesf[2];
    onesf[0] = (g == 0) ? 0x3C003C00u : 0u;
    onesf[1] = onesf[0];

    const int rb = w * 16;

    uint32_t qf[4][4];
    #pragma unroll
    for (int kk = 0; kk < 4; kk++) {
        int r  = rb + (lane & 15);
        int gg = kk*2 + (lane >> 4);
        ldsm_x4(qf[kk], Qs + r*128 + 16*(gg ^ (r & 7)));
    }

    float acc_o[8][4];
    #pragma unroll
    for (int ni = 0; ni < 8; ni++)
        #pragma unroll
        for (int c = 0; c < 4; c++) acc_o[ni][c] = 0.f;
    float acc_l[4] = {0.f, 0.f, 0.f, 0.f};
    float m0 = -1e30f, m1 = -1e30f;

    const int nch = rb/64 + 1;
    for (int c = 0; c < nch; c++) {
        float s[8][4];
        #pragma unroll
        for (int ni = 0; ni < 8; ni++)
            #pragma unroll
            for (int cc = 0; cc < 4; cc++) s[ni][cc] = 0.f;

        #pragma unroll
        for (int kk = 0; kk < 4; kk++) {
            uint32_t kf[8][2];
            #pragma unroll
            for (int nb = 0; nb < 4; nb++) {
                int r  = c*64 + nb*16 + (lane & 15);
                int gg = kk*2 + (lane >> 4);
                uint32_t tmp[4];
                ldsm_x4(tmp, Ks + r*128 + 16*(gg ^ (r & 7)));
                kf[nb*2][0]   = tmp[0]; kf[nb*2][1]   = tmp[2];
                kf[nb*2+1][0] = tmp[1]; kf[nb*2+1][1] = tmp[3];
            }
            #pragma unroll
            for (int ni = 0; ni < 8; ni++)
                mma_f16(s[ni], qf[kk], kf[ni]);
        }

        if (c == nch - 1) {
            int r0 = rb + g;
            #pragma unroll
            for (int ni = 0; ni < 8; ni++) {
                int col = c*64 + ni*8 + t*2;
                if (col     > r0)     s[ni][0] = -1e30f;
                if (col + 1 > r0)     s[ni][1] = -1e30f;
                if (col     > r0 + 8) s[ni][2] = -1e30f;
                if (col + 1 > r0 + 8) s[ni][3] = -1e30f;
            }
        }

        float mx0 = -1e30f, mx1 = -1e30f;
        #pragma unroll
        for (int ni = 0; ni < 8; ni++) {
            mx0 = fmaxf(mx0, fmaxf(s[ni][0], s[ni][1]));
            mx1 = fmaxf(mx1, fmaxf(s[ni][2], s[ni][3]));
        }
        mx0 = fmaxf(mx0, __shfl_xor_sync(0xffffffffu, mx0, 1));
        mx0 = fmaxf(mx0, __shfl_xor_sync(0xffffffffu, mx0, 2));
        mx1 = fmaxf(mx1, __shfl_xor_sync(0xffffffffu, mx1, 1));
        mx1 = fmaxf(mx1, __shfl_xor_sync(0xffffffffu, mx1, 2));
        float mn0 = fmaxf(m0, mx0);
        float mn1 = fmaxf(m1, mx1);
        float c0 = exp2f((m0 - mn0) * kscale);
        float c1 = exp2f((m1 - mn1) * kscale);
        m0 = mn0; m1 = mn1;
        float mk0 = mn0 * kscale;
        float mk1 = mn1 * kscale;
        #pragma unroll
        for (int ni = 0; ni < 8; ni++) {
            acc_o[ni][0] *= c0; acc_o[ni][1] *= c0;
            acc_o[ni][2] *= c1; acc_o[ni][3] *= c1;
        }
        acc_l[0] *= c0; acc_l[1] *= c0;
        acc_l[2] *= c1; acc_l[3] *= c1;

        #pragma unroll
        for (int kk2 = 0; kk2 < 4; kk2++) {
            uint32_t pa[4];
            #pragma unroll
            for (int q = 0; q < 2; q++) {
                int ni = kk2*2 + q;
                float e0 = exp2f(s[ni][0]*kscale - mk0);
                float e1 = exp2f(s[ni][1]*kscale - mk0);
                float e2 = exp2f(s[ni][2]*kscale - mk1);
                float e3 = exp2f(s[ni][3]*kscale - mk1);
                __half2 h01 = __floats2half2_rn(e0, e1);
                __half2 h23 = __floats2half2_rn(e2, e3);
                pa[q*2 + 0] = *(uint32_t*)&h01;
                pa[q*2 + 1] = *(uint32_t*)&h23;
            }
            uint32_t vf[8][2];
            #pragma unroll
            for (int nb = 0; nb < 4; nb++) {
                int k  = c*64 + kk2*16 + (lane & 15);
                int gg = nb*2 + (lane >> 4);
                uint32_t tmp[4];
                ldsm_x4_t(tmp, Vs + k*128 + 16*(gg ^ (k & 7)));
                vf[nb*2][0]   = tmp[0]; vf[nb*2][1]   = tmp[1];
                vf[nb*2+1][0] = tmp[2]; vf[nb*2+1][1] = tmp[3];
            }
            mma_f16(acc_l, pa, onesf);
            #pragma unroll
            for (int dn = 0; dn < 8; dn++)
                mma_f16(acc_o[dn], pa, vf[dn]);
        }
    }

    float l0 = __shfl_sync(0xffffffffu, acc_l[0], lane & ~3);
    float l1 = __shfl_sync(0xffffffffu, acc_l[2], lane & ~3);
    float r0 = 1.0f / l0;
    float r1 = 1.0f / l1;
    int row = rb + g;
    __half* op0 = o + (size_t)(b*TT + row)     * EE + h*DD;
    __half* op1 = o + (size_t)(b*TT + row + 8) * EE + h*DD;
    #pragma unroll
    for (int ni = 0; ni < 8; ni++) {
        *(__half2*)(op0 + ni*8 + t*2) =
            __floats2half2_rn(acc_o[ni][0]*r0, acc_o[ni][1]*r0);
        *(__half2*)(op1 + ni*8 + t*2) =
            __floats2half2_rn(acc_o[ni][2]*r1, acc_o[ni][3]*r1);
    }
}

// ---------------- launcher ----------------
extern "C" void kernel_launch(void* const* d_in, const int* in_sizes, int n_in,
                              void* d_out, int out_size)
{
    (void)in_sizes; (void)n_in; (void)out_size;
    const int*   idx  = (const int*)  d_in[0];
    const float* tok  = (const float*)d_in[1];
    const float* pos  = (const float*)d_in[2];
    const float* Wq   = (const float*)d_in[3];
    const float* Wk   = (const float*)d_in[4];
    const float* Wv   = (const float*)d_in[5];
    const float* Wo   = (const float*)d_in[6];
    const float* bo   = (const float*)d_in[7];
    const float* ln1s = (const float*)d_in[8];
    const float* ln1b = (const float*)d_in[9];
    const float* ln2s = (const float*)d_in[10];
    const float* ln2b = (const float*)d_in[11];
    const float* W1   = (const float*)d_in[12];
    const float* b1   = (const float*)d_in[13];
    const float* W2   = (const float*)d_in[14];
    const float* b2   = (const float*)d_in[15];
    const float* lnfs = (const float*)d_in[16];
    const float* lnfb = (const float*)d_in[17];
    const float* Wh   = (const float*)d_in[18];
    const float* bh   = (const float*)d_in[19];
    float* out = (float*)d_out;

    float *x;
    __half *qkv, *h, *ao, *ff, *wqkv, *wo, *w1, *w2, *wh;
    cudaGetSymbolAddress((void**)&x,    g_x);
    cudaGetSymbolAddress((void**)&qkv,  g_qkv);
    cudaGetSymbolAddress((void**)&h,    g_h);
    cudaGetSymbolAddress((void**)&ao,   g_ao);
    cudaGetSymbolAddress((void**)&ff,   g_ff);
    cudaGetSymbolAddress((void**)&wqkv, g_wqkv);
    cudaGetSymbolAddress((void**)&wo,   g_wo);
    cudaGetSymbolAddress((void**)&w1,   g_w1);
    cudaGetSymbolAddress((void**)&w2,   g_w2);
    cudaGetSymbolAddress((void**)&wh,   g_wh);

    const int SM128 = 3*(ATILE + 64*128*2);   // 96 KB
    const int SM64  = 3*STAGE64;              // 72 KB
    cudaFuncSetAttribute(hgemm_kernel<128,3>, cudaFuncAttributeMaxDynamicSharedMemorySize, SM128);
    cudaFuncSetAttribute(hgemm_wide_kernel<0>, cudaFuncAttributeMaxDynamicSharedMemorySize, SMW);
    cudaFuncSetAttribute(hgemm_wide_kernel<2>, cudaFuncAttributeMaxDynamicSharedMemorySize, SMW);
    cudaFuncSetAttribute(hgemm64_kernel, cudaFuncAttributeMaxDynamicSharedMemorySize, SM64);
    cudaFuncSetAttribute(fattn_kernel, cudaFuncAttributeMaxDynamicSharedMemorySize, FA_SMEM);

    embed_kernel<<<(MM*EE + 255)/256, 256>>>(idx, tok, pos, x);
    pack_qkv_half<<<(LL*EE*E3/2 + 255)/256, 256>>>(Wq, Wk, Wv, wqkv);
    {
        int ntot = (LL*EE*EE + LL*EE*FF + LL*FF*EE + EE*VVOC) / 2;
        prep4_kernel<<<(ntot + 255)/256, 256>>>(Wo, W1, W2, Wh, wo, w1, w2, wh);
    }

    dim3 gQKV(E3/128, MM/128);    // 9 x 64
    dim3 gE64(EE/128, MM/64);     // 3 x 128
    dim3 gF(FF/256, MM/128);      // 6 x 64
    dim3 gV(VVOC/256, MM/128);    // 125 x 64

    for (int l = 0; l < LL; l++) {
        ln_kernel<<<MM/8, 256>>>(x, h, ln1s + l*EE, ln1b + l*EE);
        hgemm_kernel<128,3><<<gQKV, 256, SM128>>>(h, wqkv + (size_t)l*EE*E3, nullptr, qkv, MM, E3, EE);
        fattn_kernel<<<BV*HH, 512, FA_SMEM>>>(qkv, ao);
        hgemm64_kernel<<<gE64, 256, SM64>>>(ao, wo + (size_t)l*EE*EE, bo + l*EE, x, MM, EE, EE);
        ln_kernel<<<MM/8, 256>>>(x, h, ln2s + l*EE, ln2b + l*EE);
        hgemm_wide_kernel<2><<<gF, 256, SMW>>>(h, w1 + (size_t)l*EE*FF, b1 + l*FF, ff, MM, FF, EE);
        hgemm64_kernel<<<gE64, 256, SM64>>>(ff, w2 + (size_t)l*FF*EE, b2 + l*EE, x, MM, EE, FF);
    }
    ln_kernel<<<MM/8, 256>>>(x, h, lnfs, lnfb);
    hgemm_wide_kernel<0><<<gV, 256, SMW>>>(h, wh, bh, out, MM, VVOC, EE);
}

// round 17
// speedup vs baseline: 1.0871x; 1.0871x over previous
#include <cuda_runtime.h>
#include <cuda_fp16.h>
#include <math.h>
#include <stdint.h>

// Problem constants
#define BV 32
#define TT 256
#define EE 384
#define HH 6
#define DD 64
#define LL 6
#define FF 1536
#define VVOC 32000
#define MM (BV*TT)   // 8192
#define E3 (3*EE)    // 1152

// ---------------- scratch ----------------
__device__ float  g_x   [MM*EE];
__device__ __half g_qkv [MM*E3];
__device__ __half g_h   [MM*EE];
__device__ __half g_ao  [MM*EE];
__device__ __half g_ff  [(size_t)MM*FF];
__device__ __half g_wqkv[LL*EE*E3];
__device__ __half g_wo  [LL*EE*EE];
__device__ __half g_w1  [LL*EE*FF];
__device__ __half g_w2  [LL*FF*EE];
__device__ __half g_wh  [(size_t)EE*VVOC];

// ---------------- PTX helpers ----------------
__device__ __forceinline__ void cp_async16(uint32_t dst, const void* src) {
    asm volatile("cp.async.cg.shared.global [%0], [%1], 16;" :: "r"(dst), "l"(src));
}
__device__ __forceinline__ void cp_commit() { asm volatile("cp.async.commit_group;"); }
template<int N>
__device__ __forceinline__ void cp_wait() { asm volatile("cp.async.wait_group %0;" :: "n"(N)); }

__device__ __forceinline__ void ldsm_x4(uint32_t* r, uint32_t a) {
    asm volatile("ldmatrix.sync.aligned.m8n8.x4.shared.b16 {%0,%1,%2,%3}, [%4];"
        : "=r"(r[0]), "=r"(r[1]), "=r"(r[2]), "=r"(r[3]) : "r"(a));
}
__device__ __forceinline__ void ldsm_x4_t(uint32_t* r, uint32_t a) {
    asm volatile("ldmatrix.sync.aligned.m8n8.x4.trans.shared.b16 {%0,%1,%2,%3}, [%4];"
        : "=r"(r[0]), "=r"(r[1]), "=r"(r[2]), "=r"(r[3]) : "r"(a));
}
__device__ __forceinline__ void mma_f16(float* c, const uint32_t* a, const uint32_t* b) {
    asm volatile(
        "mma.sync.aligned.m16n8k16.row.col.f32.f16.f16.f32 "
        "{%0,%1,%2,%3}, {%4,%5,%6,%7}, {%8,%9}, {%0,%1,%2,%3};"
        : "+f"(c[0]), "+f"(c[1]), "+f"(c[2]), "+f"(c[3])
        : "r"(a[0]), "r"(a[1]), "r"(a[2]), "r"(a[3]), "r"(b[0]), "r"(b[1]));
}

// ---------------- embedding ----------------
__global__ void embed_kernel(const int* __restrict__ idx, const float* __restrict__ tok,
                             const float* __restrict__ pos, float* __restrict__ x)
{
    int i = blockIdx.x * blockDim.x + threadIdx.x;
    if (i >= MM*EE) return;
    int e   = i % EE;
    int row = i / EE;
    int t   = row % TT;
    x[i] = tok[(size_t)idx[row]*EE + e] + pos[t*EE + e];
}

// ---------------- weight prep (vectorized x2) ----------------
__global__ void pack_qkv_half(const float* __restrict__ Wq, const float* __restrict__ Wk,
                              const float* __restrict__ Wv, __half* __restrict__ out)
{
    int i = blockIdx.x * blockDim.x + threadIdx.x;   // pair index
    if (i >= LL*EE*E3/2) return;
    int e2 = i * 2;
    int c  = e2 % E3;
    int re = e2 / E3;
    int sel = c / EE;       // pair never straddles a 384 boundary
    int cc  = c % EE;
    const float* src = (sel == 0) ? Wq : (sel == 1) ? Wk : Wv;
    float2 v = *(const float2*)(src + (size_t)re*EE + cc);
    *(__half2*)(out + e2) = __floats2half2_rn(v.x, v.y);
}

__global__ void prep4_kernel(const float* __restrict__ Wo, const float* __restrict__ W1,
                             const float* __restrict__ W2, const float* __restrict__ Wh,
                             __half* __restrict__ wo, __half* __restrict__ w1,
                             __half* __restrict__ w2, __half* __restrict__ wh)
{
    const int N0 = LL*EE*EE/2, N1 = LL*EE*FF/2, N2 = LL*FF*EE/2;
    const int NH = EE*VVOC/2;
    int i = blockIdx.x * blockDim.x + threadIdx.x;
    const float* s; __half* d;
    if      (i < N0)                 { s = Wo; d = wo; }
    else if ((i -= N0) < N1)         { s = W1; d = w1; }
    else if ((i -= N1) < N2)         { s = W2; d = w2; }
    else if ((i -= N2) < NH)         { s = Wh; d = wh; }
    else return;
    float2 v = *(const float2*)(s + (size_t)i*2);
    *(__half2*)(d + (size_t)i*2) = __floats2half2_rn(v.x, v.y);
}

// ---------------- layernorm: one warp per row ----------------
__global__ void ln_kernel(const float* __restrict__ in, __half* __restrict__ out,
                          const float* __restrict__ s, const float* __restrict__ b)
{
    int warp = threadIdx.x >> 5, lane = threadIdx.x & 31;
    int row  = blockIdx.x * 8 + warp;
    const float4* xr = (const float4*)(in + (size_t)row*EE);
    float4 v[3];
    float ls = 0.f, lq = 0.f;
    #pragma unroll
    for (int k = 0; k < 3; k++) {
        v[k] = xr[lane + 32*k];
        ls += (v[k].x + v[k].y) + (v[k].z + v[k].w);
        lq += (v[k].x*v[k].x + v[k].y*v[k].y) + (v[k].z*v[k].z + v[k].w*v[k].w);
    }
    #pragma unroll
    for (int o = 16; o > 0; o >>= 1) {
        ls += __shfl_xor_sync(0xffffffffu, ls, o);
        lq += __shfl_xor_sync(0xffffffffu, lq, o);
    }
    float mean = ls * (1.0f/EE);
    float var  = lq * (1.0f/EE) - mean*mean;
    float inv  = rsqrtf(var + 1e-5f);
    #pragma unroll
    for (int k = 0; k < 3; k++) {
        int c4 = lane + 32*k;
        float4 s4 = ((const float4*)s)[c4];
        float4 b4 = ((const float4*)b)[c4];
        float o0 = (v[k].x - mean) * inv * s4.x + b4.x;
        float o1 = (v[k].y - mean) * inv * s4.y + b4.y;
        float o2 = (v[k].z - mean) * inv * s4.z + b4.z;
        float o3 = (v[k].w - mean) * inv * s4.w + b4.w;
        __half2* op = (__half2*)(out + (size_t)row*EE + c4*4);
        op[0] = __floats2half2_rn(o0, o1);
        op[1] = __floats2half2_rn(o2, o3);
    }
}

// ---------------- fp16 tensor-core GEMM (BM=128, BN=128, warp 32x64) ----------------
// MODE: 0 = f32 store, 1 = f32 accumulate into C, 2 = relu->fp16, 3 = fp16 store
#define ATILE 16384

template<int BN, int MODE>
__global__ void __launch_bounds__(256, 2)
hgemm_kernel(const __half* __restrict__ A, const __half* __restrict__ B,
             const float* __restrict__ bias, void* __restrict__ Cv,
             int M, int N, int K)
{
    constexpr int T     = 256;
    constexpr int NST   = 3;
    constexpr int BTILE = 64 * BN * 2;
    constexpr int STAGE = ATILE + BTILE;
    constexpr int ITERA = 1024 / T;
    constexpr int ITERB = (8 * BN) / T;

    extern __shared__ char smem[];
    const uint32_t sb = (uint32_t)__cvta_generic_to_shared(smem);

    const int tid  = threadIdx.x;
    const int lane = tid & 31;
    const int wid  = tid >> 5;
    const int wm   = wid & 3;
    const int wn   = wid >> 2;
    const int g    = lane >> 2;
    const int t    = lane & 3;

    const int row0 = blockIdx.y * 128;
    const int col0 = blockIdx.x * BN;
    const int KT   = K >> 6;

    auto issue = [&](int kt) {
        uint32_t st = sb + (uint32_t)(kt % NST) * STAGE;
        #pragma unroll
        for (int i = 0; i < ITERA; i++) {
            int c = tid + T*i;
            int r = c >> 3, gg = c & 7;
            cp_async16(st + r*128 + 16*(gg ^ (r&7)),
                       A + (size_t)(row0 + r)*K + kt*64 + gg*8);
        }
        #pragma unroll
        for (int i = 0; i < ITERB; i++) {
            int c = tid + T*i;
            int k = c / (BN/8), gg = c % (BN/8);
            cp_async16(st + ATILE + k*(BN*2) + 16*(gg ^ (k&7)),
                       B + (size_t)(kt*64 + k)*N + col0 + gg*8);
        }
        cp_commit();
    };

    float acc[2][8][4];
    #pragma unroll
    for (int mi = 0; mi < 2; mi++)
        #pragma unroll
        for (int ni = 0; ni < 8; ni++)
            #pragma unroll
            for (int r = 0; r < 4; r++) acc[mi][ni][r] = 0.f;

    issue(0); issue(1);

    for (int kt = 0; kt < KT; kt++) {
        cp_wait<1>();
        __syncthreads();
        if (kt + 2 < KT) issue(kt + 2);

        const uint32_t a_st = sb + (uint32_t)(kt % NST) * STAGE;
        const uint32_t b_st = a_st + ATILE;

        #pragma unroll
        for (int ks = 0; ks < 4; ks++) {
            uint32_t af[2][4], bf[8][2];
            #pragma unroll
            for (int mi = 0; mi < 2; mi++) {
                int m  = wm*32 + mi*16 + (lane & 15);
                int gg = ks*2 + (lane >> 4);
                ldsm_x4(af[mi], a_st + m*128 + 16*(gg ^ (m&7)));
            }
            #pragma unroll
            for (int np = 0; np < 4; np++) {
                int k  = ks*16 + (lane & 15);
                int gg = (wn*64 + np*16)/8 + (lane >> 4);
                uint32_t tmp[4];
                ldsm_x4_t(tmp, b_st + k*(BN*2) + 16*(gg ^ (k&7)));
                bf[np*2][0]   = tmp[0]; bf[np*2][1]   = tmp[1];
                bf[np*2+1][0] = tmp[2]; bf[np*2+1][1] = tmp[3];
            }
            #pragma unroll
            for (int mi = 0; mi < 2; mi++)
                #pragma unroll
                for (int ni = 0; ni < 8; ni++)
                    mma_f16(acc[mi][ni], af[mi], bf[ni]);
        }
    }

    __syncthreads();

    #pragma unroll
    for (int mi = 0; mi < 2; mi++) {
        #pragma unroll
        for (int ni = 0; ni < 8; ni++) {
            int row = row0 + wm*32 + mi*16 + g;
            int col = col0 + wn*64 + ni*8 + t*2;
            float v0 = acc[mi][ni][0], v1 = acc[mi][ni][1];
            float v2 = acc[mi][ni][2], v3 = acc[mi][ni][3];
            if (bias) {
                float b0 = bias[col], b1 = bias[col+1];
                v0 += b0; v1 += b1; v2 += b0; v3 += b1;
            }
            if (MODE == 2 || MODE == 3) {
                if (MODE == 2) {
                    v0 = fmaxf(v0, 0.f); v1 = fmaxf(v1, 0.f);
                    v2 = fmaxf(v2, 0.f); v3 = fmaxf(v3, 0.f);
                }
                __half* C = (__half*)Cv;
                *(__half2*)(C + (size_t)row * N + col)     = __floats2half2_rn(v0, v1);
                *(__half2*)(C + (size_t)(row+8) * N + col) = __floats2half2_rn(v2, v3);
            } else {
                float* C = (float*)Cv;
                float* c0 = C + (size_t)row * N + col;
                float* c1 = C + (size_t)(row + 8) * N + col;
                if (MODE == 1) {
                    float2 o0 = *(const float2*)c0;
                    float2 o1 = *(const float2*)c1;
                    v0 += o0.x; v1 += o0.y; v2 += o1.x; v3 += o1.y;
                }
                *(float2*)c0 = make_float2(v0, v1);
                *(float2*)c1 = make_float2(v2, v3);
            }
        }
    }
}

// ---------------- fp16 GEMM wide: BM=128 x BN=256, 8 warps, warp tile 64x64, NST=3 ----
// MODE: 0 = f32 store (+bias), 2 = relu -> fp16 store (+bias)
#define BTILEW (64*256*2)          // 32768
#define STAGEW (ATILE + BTILEW)    // 49152
#define SMW (3*STAGEW)             // 147456

template<int MODE>
__global__ void __launch_bounds__(256, 1)
hgemm_wide_kernel(const __half* __restrict__ A, const __half* __restrict__ B,
                  const float* __restrict__ bias, void* __restrict__ Cv,
                  int M, int N, int K)
{
    constexpr int NST = 3;
    extern __shared__ char smem[];
    const uint32_t sb = (uint32_t)__cvta_generic_to_shared(smem);

    const int tid  = threadIdx.x;
    const int lane = tid & 31;
    const int wid  = tid >> 5;
    const int wm   = wid >> 2;
    const int wn   = wid & 3;
    const int g    = lane >> 2;
    const int t    = lane & 3;

    const int row0 = blockIdx.y * 128;
    const int col0 = blockIdx.x * 256;
    const int KT   = K >> 6;

    auto issue = [&](int kt) {
        uint32_t st = sb + (uint32_t)(kt % NST) * STAGEW;
        #pragma unroll
        for (int i = 0; i < 4; i++) {
            int c = tid + 256*i;
            int r = c >> 3, gg = c & 7;
            cp_async16(st + r*128 + 16*(gg ^ (r&7)),
                       A + (size_t)(row0 + r)*K + kt*64 + gg*8);
        }
        #pragma unroll
        for (int i = 0; i < 8; i++) {
            int c = tid + 256*i;
            int k = c >> 5, gg = c & 31;
            cp_async16(st + ATILE + k*512 + 16*(gg ^ (k&7)),
                       B + (size_t)(kt*64 + k)*N + col0 + gg*8);
        }
        cp_commit();
    };

    float acc[4][8][4];
    #pragma unroll
    for (int mi = 0; mi < 4; mi++)
        #pragma unroll
        for (int ni = 0; ni < 8; ni++)
            #pragma unroll
            for (int r = 0; r < 4; r++) acc[mi][ni][r] = 0.f;

    issue(0); issue(1);

    for (int kt = 0; kt < KT; kt++) {
        cp_wait<1>();
        __syncthreads();
        if (kt + 2 < KT) issue(kt + 2);

        const uint32_t a_st = sb + (uint32_t)(kt % NST) * STAGEW;
        const uint32_t b_st = a_st + ATILE;

        #pragma unroll
        for (int ks = 0; ks < 4; ks++) {
            uint32_t af[4][4], bf[8][2];
            #pragma unroll
            for (int mi = 0; mi < 4; mi++) {
                int m  = wm*64 + mi*16 + (lane & 15);
                int gg = ks*2 + (lane >> 4);
                ldsm_x4(af[mi], a_st + m*128 + 16*(gg ^ (m&7)));
            }
            #pragma unroll
            for (int np = 0; np < 4; np++) {
                int k  = ks*16 + (lane & 15);
                int gg = wn*8 + np*2 + (lane >> 4);
                uint32_t tmp[4];
                ldsm_x4_t(tmp, b_st + k*512 + 16*(gg ^ (k&7)));
                bf[np*2][0]   = tmp[0]; bf[np*2][1]   = tmp[1];
                bf[np*2+1][0] = tmp[2]; bf[np*2+1][1] = tmp[3];
            }
            #pragma unroll
            for (int mi = 0; mi < 4; mi++)
                #pragma unroll
                for (int ni = 0; ni < 8; ni++)
                    mma_f16(acc[mi][ni], af[mi], bf[ni]);
        }
    }

    __syncthreads();

    #pragma unroll
    for (int mi = 0; mi < 4; mi++) {
        #pragma unroll
        for (int ni = 0; ni < 8; ni++) {
            int row = row0 + wm*64 + mi*16 + g;
            int col = col0 + wn*64 + ni*8 + t*2;
            float v0 = acc[mi][ni][0], v1 = acc[mi][ni][1];
            float v2 = acc[mi][ni][2], v3 = acc[mi][ni][3];
            if (bias) {
                float b0 = bias[col], b1 = bias[col+1];
                v0 += b0; v1 += b1; v2 += b0; v3 += b1;
            }
            if (MODE == 2) {
                v0 = fmaxf(v0, 0.f); v1 = fmaxf(v1, 0.f);
                v2 = fmaxf(v2, 0.f); v3 = fmaxf(v3, 0.f);
                __half* C = (__half*)Cv;
                *(__half2*)(C + (size_t)row * N + col)     = __floats2half2_rn(v0, v1);
                *(__half2*)(C + (size_t)(row+8) * N + col) = __floats2half2_rn(v2, v3);
            } else {
                float* C = (float*)Cv;
                *(float2*)(C + (size_t)row * N + col)       = make_float2(v0, v1);
                *(float2*)(C + (size_t)(row + 8) * N + col) = make_float2(v2, v3);
            }
        }
    }
}

// ---------------- fp16 GEMM, BM=64 x BN=128 (wave-friendly, accumulate mode) ----
#define ATILE64 8192
#define STAGE64 (ATILE64 + 16384)

__global__ void __launch_bounds__(256, 2)
hgemm64_kernel(const __half* __restrict__ A, const __half* __restrict__ B,
               const float* __restrict__ bias, float* __restrict__ C,
               int M, int N, int K)
{
    constexpr int NST = 3;
    extern __shared__ char smem[];
    const uint32_t sb = (uint32_t)__cvta_generic_to_shared(smem);

    const int tid  = threadIdx.x;
    const int lane = tid & 31;
    const int wid  = tid >> 5;
    const int wm   = wid & 1;
    const int wn   = wid >> 1;
    const int g    = lane >> 2;
    const int t    = lane & 3;

    const int row0 = blockIdx.y * 64;
    const int col0 = blockIdx.x * 128;
    const int KT   = K >> 6;

    auto issue = [&](int kt) {
        uint32_t st = sb + (uint32_t)(kt % NST) * STAGE64;
        #pragma unroll
        for (int i = 0; i < 2; i++) {
            int c = tid + 256*i;
            int r = c >> 3, gg = c & 7;
            cp_async16(st + r*128 + 16*(gg ^ (r&7)),
                       A + (size_t)(row0 + r)*K + kt*64 + gg*8);
        }
        #pragma unroll
        for (int i = 0; i < 4; i++) {
            int c = tid + 256*i;
            int k = c >> 4, gg = c & 15;
            cp_async16(st + ATILE64 + k*256 + 16*(gg ^ (k&7)),
                       B + (size_t)(kt*64 + k)*N + col0 + gg*8);
        }
        cp_commit();
    };

    float acc[2][4][4];
    #pragma unroll
    for (int mi = 0; mi < 2; mi++)
        #pragma unroll
        for (int ni = 0; ni < 4; ni++)
            #pragma unroll
            for (int r = 0; r < 4; r++) acc[mi][ni][r] = 0.f;

    issue(0); issue(1);

    for (int kt = 0; kt < KT; kt++) {
        cp_wait<1>();
        __syncthreads();
        if (kt + 2 < KT) issue(kt + 2);

        const uint32_t a_st = sb + (uint32_t)(kt % NST) * STAGE64;
        const uint32_t b_st = a_st + ATILE64;

        #pragma unroll
        for (int ks = 0; ks < 4; ks++) {
            uint32_t af[2][4], bf[4][2];
            #pragma unroll
            for (int mi = 0; mi < 2; mi++) {
                int m  = wm*32 + mi*16 + (lane & 15);
                int gg = ks*2 + (lane >> 4);
                ldsm_x4(af[mi], a_st + m*128 + 16*(gg ^ (m&7)));
            }
            #pragma unroll
            for (int np = 0; np < 2; np++) {
                int k  = ks*16 + (lane & 15);
                int gg = (wn*32 + np*16)/8 + (lane >> 4);
                uint32_t tmp[4];
                ldsm_x4_t(tmp, b_st + k*256 + 16*(gg ^ (k&7)));
                bf[np*2][0]   = tmp[0]; bf[np*2][1]   = tmp[1];
                bf[np*2+1][0] = tmp[2]; bf[np*2+1][1] = tmp[3];
            }
            #pragma unroll
            for (int mi = 0; mi < 2; mi++)
                #pragma unroll
                for (int ni = 0; ni < 4; ni++)
                    mma_f16(acc[mi][ni], af[mi], bf[ni]);
        }
    }

    __syncthreads();

    #pragma unroll
    for (int mi = 0; mi < 2; mi++) {
        #pragma unroll
        for (int ni = 0; ni < 4; ni++) {
            int row = row0 + wm*32 + mi*16 + g;
            int col = col0 + wn*32 + ni*8 + t*2;
            float v0 = acc[mi][ni][0], v1 = acc[mi][ni][1];
            float v2 = acc[mi][ni][2], v3 = acc[mi][ni][3];
            if (bias) {
                float b0 = bias[col], b1 = bias[col+1];
                v0 += b0; v1 += b1; v2 += b0; v3 += b1;
            }
            float* c0 = C + (size_t)row * N + col;
            float* c1 = C + (size_t)(row + 8) * N + col;
            float2 o0 = *(const float2*)c0;
            float2 o1 = *(const float2*)c1;
            *(float2*)c0 = make_float2(v0 + o0.x, v1 + o0.y);
            *(float2*)c1 = make_float2(v2 + o1.x, v3 + o1.y);
        }
    }
}

// ---------------- flash attention: 512 threads, one 16-row tile per warp ----
#define FA_SMEM 98304

__global__ void __launch_bounds__(512)
fattn_kernel(const __half* __restrict__ qkv, __half* __restrict__ o)
{
    extern __shared__ char sm[];
    const uint32_t sb = (uint32_t)__cvta_generic_to_shared(sm);
    const uint32_t Qs = sb, Ks = sb + 32768, Vs = sb + 65536;

    const int b = blockIdx.x / HH;
    const int h = blockIdx.x % HH;
    const int tid  = threadIdx.x;
    const int lane = tid & 31;
    const int w    = tid >> 5;
    const int g    = lane >> 2;
    const int t    = lane & 3;

    const __half* base = qkv + (size_t)b*TT*E3 + h*DD;
    #pragma unroll
    for (int i = 0; i < 12; i++) {
        int idx = tid + 512*i;
        int sec = idx >> 11;
        int rem = idx & 2047;
        int seq = rem >> 3, c8 = rem & 7;
        uint32_t dst = sb + sec*32768 + seq*128 + 16*(c8 ^ (seq & 7));
        cp_async16(dst, base + (size_t)seq*E3 + sec*EE + c8*8);
    }
    cp_commit();
    cp_wait<0>();
    __syncthreads();

    const float kscale = 0.125f * 1.44269504f;
    uint32_t onesf[2];
    onesf[0] = (g == 0) ? 0x3C003C00u : 0u;
    onesf[1] = onesf[0];

    const int rb = w * 16;

    uint32_t qf[4][4];
    #pragma unroll
    for (int kk = 0; kk < 4; kk++) {
        int r  = rb + (lane & 15);
        int gg = kk*2 + (lane >> 4);
        ldsm_x4(qf[kk], Qs + r*128 + 16*(gg ^ (r & 7)));
    }

    float acc_o[8][4];
    #pragma unroll
    for (int ni = 0; ni < 8; ni++)
        #pragma unroll
        for (int c = 0; c < 4; c++) acc_o[ni][c] = 0.f;
    float acc_l[4] = {0.f, 0.f, 0.f, 0.f};
    float m0 = -1e30f, m1 = -1e30f;

    const int nch = rb/64 + 1;
    for (int c = 0; c < nch; c++) {
        float s[8][4];
        #pragma unroll
        for (int ni = 0; ni < 8; ni++)
            #pragma unroll
            for (int cc = 0; cc < 4; cc++) s[ni][cc] = 0.f;

        #pragma unroll
        for (int kk = 0; kk < 4; kk++) {
            uint32_t kf[8][2];
            #pragma unroll
            for (int nb = 0; nb < 4; nb++) {
                int r  = c*64 + nb*16 + (lane & 15);
                int gg = kk*2 + (lane >> 4);
                uint32_t tmp[4];
                ldsm_x4(tmp, Ks + r*128 + 16*(gg ^ (r & 7)));
                kf[nb*2][0]   = tmp[0]; kf[nb*2][1]   = tmp[2];
                kf[nb*2+1][0] = tmp[1]; kf[nb*2+1][1] = tmp[3];
            }
            #pragma unroll
            for (int ni = 0; ni < 8; ni++)
                mma_f16(s[ni], qf[kk], kf[ni]);
        }

        if (c == nch - 1) {
            int r0 = rb + g;
            #pragma unroll
            for (int ni = 0; ni < 8; ni++) {
                int col = c*64 + ni*8 + t*2;
                if (col     > r0)     s[ni][0] = -1e30f;
                if (col + 1 > r0)     s[ni][1] = -1e30f;
                if (col     > r0 + 8) s[ni][2] = -1e30f;
                if (col + 1 > r0 + 8) s[ni][3] = -1e30f;
            }
        }

        float mx0 = -1e30f, mx1 = -1e30f;
        #pragma unroll
        for (int ni = 0; ni < 8; ni++) {
            mx0 = fmaxf(mx0, fmaxf(s[ni][0], s[ni][1]));
            mx1 = fmaxf(mx1, fmaxf(s[ni][2], s[ni][3]));
        }
        mx0 = fmaxf(mx0, __shfl_xor_sync(0xffffffffu, mx0, 1));
        mx0 = fmaxf(mx0, __shfl_xor_sync(0xffffffffu, mx0, 2));
        mx1 = fmaxf(mx1, __shfl_xor_sync(0xffffffffu, mx1, 1));
        mx1 = fmaxf(mx1, __shfl_xor_sync(0xffffffffu, mx1, 2));
        float mn0 = fmaxf(m0, mx0);
        float mn1 = fmaxf(m1, mx1);
        float c0 = exp2f((m0 - mn0) * kscale);
        float c1 = exp2f((m1 - mn1) * kscale);
        m0 = mn0; m1 = mn1;
        float mk0 = mn0 * kscale;
        float mk1 = mn1 * kscale;
        #pragma unroll
        for (int ni = 0; ni < 8; ni++) {
            acc_o[ni][0] *= c0; acc_o[ni][1] *= c0;
            acc_o[ni][2] *= c1; acc_o[ni][3] *= c1;
        }
        acc_l[0] *= c0; acc_l[1] *= c0;
        acc_l[2] *= c1; acc_l[3] *= c1;

        #pragma unroll
        for (int kk2 = 0; kk2 < 4; kk2++) {
            uint32_t pa[4];
            #pragma unroll
            for (int q = 0; q < 2; q++) {
                int ni = kk2*2 + q;
                float e0 = exp2f(s[ni][0]*kscale - mk0);
                float e1 = exp2f(s[ni][1]*kscale - mk0);
                float e2 = exp2f(s[ni][2]*kscale - mk1);
                float e3 = exp2f(s[ni][3]*kscale - mk1);
                __half2 h01 = __floats2half2_rn(e0, e1);
                __half2 h23 = __floats2half2_rn(e2, e3);
                pa[q*2 + 0] = *(uint32_t*)&h01;
                pa[q*2 + 1] = *(uint32_t*)&h23;
            }
            uint32_t vf[8][2];
            #pragma unroll
            for (int nb = 0; nb < 4; nb++) {
                int k  = c*64 + kk2*16 + (lane & 15);
                int gg = nb*2 + (lane >> 4);
                uint32_t tmp[4];
                ldsm_x4_t(tmp, Vs + k*128 + 16*(gg ^ (k & 7)));
                vf[nb*2][0]   = tmp[0]; vf[nb*2][1]   = tmp[1];
                vf[nb*2+1][0] = tmp[2]; vf[nb*2+1][1] = tmp[3];
            }
            mma_f16(acc_l, pa, onesf);
            #pragma unroll
            for (int dn = 0; dn < 8; dn++)
                mma_f16(acc_o[dn], pa, vf[dn]);
        }
    }

    float l0 = __shfl_sync(0xffffffffu, acc_l[0], lane & ~3);
    float l1 = __shfl_sync(0xffffffffu, acc_l[2], lane & ~3);
    float r0 = 1.0f / l0;
    float r1 = 1.0f / l1;
    int row = rb + g;
    __half* op0 = o + (size_t)(b*TT + row)     * EE + h*DD;
    __half* op1 = o + (size_t)(b*TT + row + 8) * EE + h*DD;
    #pragma unroll
    for (int ni = 0; ni < 8; ni++) {
        *(__half2*)(op0 + ni*8 + t*2) =
            __floats2half2_rn(acc_o[ni][0]*r0, acc_o[ni][1]*r0);
        *(__half2*)(op1 + ni*8 + t*2) =
            __floats2half2_rn(acc_o[ni][2]*r1, acc_o[ni][3]*r1);
    }
}

// ---------------- launcher ----------------
extern "C" void kernel_launch(void* const* d_in, const int* in_sizes, int n_in,
                              void* d_out, int out_size)
{
    (void)in_sizes; (void)n_in; (void)out_size;
    const int*   idx  = (const int*)  d_in[0];
    const float* tok  = (const float*)d_in[1];
    const float* pos  = (const float*)d_in[2];
    const float* Wq   = (const float*)d_in[3];
    const float* Wk   = (const float*)d_in[4];
    const float* Wv   = (const float*)d_in[5];
    const float* Wo   = (const float*)d_in[6];
    const float* bo   = (const float*)d_in[7];
    const float* ln1s = (const float*)d_in[8];
    const float* ln1b = (const float*)d_in[9];
    const float* ln2s = (const float*)d_in[10];
    const float* ln2b = (const float*)d_in[11];
    const float* W1   = (const float*)d_in[12];
    const float* b1   = (const float*)d_in[13];
    const float* W2   = (const float*)d_in[14];
    const float* b2   = (const float*)d_in[15];
    const float* lnfs = (const float*)d_in[16];
    const float* lnfb = (const float*)d_in[17];
    const float* Wh   = (const float*)d_in[18];
    const float* bh   = (const float*)d_in[19];
    float* out = (float*)d_out;

    float *x;
    __half *qkv, *h, *ao, *ff, *wqkv, *wo, *w1, *w2, *wh;
    cudaGetSymbolAddress((void**)&x,    g_x);
    cudaGetSymbolAddress((void**)&qkv,  g_qkv);
    cudaGetSymbolAddress((void**)&h,    g_h);
    cudaGetSymbolAddress((void**)&ao,   g_ao);
    cudaGetSymbolAddress((void**)&ff,   g_ff);
    cudaGetSymbolAddress((void**)&wqkv, g_wqkv);
    cudaGetSymbolAddress((void**)&wo,   g_wo);
    cudaGetSymbolAddress((void**)&w1,   g_w1);
    cudaGetSymbolAddress((void**)&w2,   g_w2);
    cudaGetSymbolAddress((void**)&wh,   g_wh);

    const int SM128 = 3*(ATILE + 64*128*2);   // 96 KB
    const int SM64  = 3*STAGE64;              // 72 KB
    cudaFuncSetAttribute(hgemm_kernel<128,3>, cudaFuncAttributeMaxDynamicSharedMemorySize, SM128);
    cudaFuncSetAttribute(hgemm_wide_kernel<0>, cudaFuncAttributeMaxDynamicSharedMemorySize, SMW);
    cudaFuncSetAttribute(hgemm_wide_kernel<2>, cudaFuncAttributeMaxDynamicSharedMemorySize, SMW);
    cudaFuncSetAttribute(hgemm64_kernel, cudaFuncAttributeMaxDynamicSharedMemorySize, SM64);
    cudaFuncSetAttribute(fattn_kernel, cudaFuncAttributeMaxDynamicSharedMemorySize, FA_SMEM);

    embed_kernel<<<(MM*EE + 255)/256, 256>>>(idx, tok, pos, x);
    pack_qkv_half<<<(LL*EE*E3/2 + 255)/256, 256>>>(Wq, Wk, Wv, wqkv);
    {
        int ntot = (LL*EE*EE + LL*EE*FF + LL*FF*EE + EE*VVOC) / 2;
        prep4_kernel<<<(ntot + 255)/256, 256>>>(Wo, W1, W2, Wh, wo, w1, w2, wh);
    }

    dim3 gQKV(E3/128, MM/128);    // 9 x 64
    dim3 gE64(EE/128, MM/64);     // 3 x 128
    dim3 gF(FF/256, MM/128);      // 6 x 64
    dim3 gV(VVOC/256, MM/128);    // 125 x 64

    for (int l = 0; l < LL; l++) {
        ln_kernel<<<MM/8, 256>>>(x, h, ln1s + l*EE, ln1b + l*EE);
        hgemm_kernel<128,3><<<gQKV, 256, SM128>>>(h, wqkv + (size_t)l*EE*E3, nullptr, qkv, MM, E3, EE);
        fattn_kernel<<<BV*HH, 512, FA_SMEM>>>(qkv, ao);
        hgemm64_kernel<<<gE64, 256, SM64>>>(ao, wo + (size_t)l*EE*EE, bo + l*EE, x, MM, EE, EE);
        ln_kernel<<<MM/8, 256>>>(x, h, ln2s + l*EE, ln2b + l*EE);
        hgemm_wide_kernel<2><<<gF, 256, SMW>>>(h, w1 + (size_t)l*EE*FF, b1 + l*FF, ff, MM, FF, EE);
        hgemm64_kernel<<<gE64, 256, SM64>>>(ff, w2 + (size_t)l*FF*EE, b2 + l*EE, x, MM, EE, FF);
    }
    ln_kernel<<<MM/8, 256>>>(x, h, lnfs, lnfb);
    hgemm_wide_kernel<0><<<gV, 256, SMW>>>(h, wh, bh, out, MM, VVOC, EE);
}